// round 5
// baseline (speedup 1.0000x reference)
#include <cuda_runtime.h>
#include <cuda_bf16.h>
#include <cstdint>

// Problem constants
#define BB   64     // batch
#define NP   900    // predictions (columns)
#define NCLS 128    // classes
#define MT   64     // targets (rows)
#define KC   8      // corners
#define INF_F 1000000000.0f

#define TLSA 256    // threads per LSA block (8 warps)
#define NPK  4      // ceil(900/256) columns per lane (tid<132 have 4, rest 3)

// Transposed cost scratch: CT[b][m][n], contiguous in n for fast row reads in LSA.
__device__ float g_CT[(size_t)BB * MT * NP];

// ---------------------------------------------------------------------------
// Kernel 1: cost matrix. One warp per (b, n). Block = 128 threads = 4 warps.
// ---------------------------------------------------------------------------
__global__ void cost_kernel(const float* __restrict__ logits,
                            const float* __restrict__ corners,
                            const int*   __restrict__ labels,
                            const float* __restrict__ boxes,
                            float* __restrict__ outC) {
    int gwarp = (blockIdx.x * blockDim.x + threadIdx.x) >> 5;
    int lane  = threadIdx.x & 31;
    int wloc  = threadIdx.x >> 5;
    if (gwarp >= BB * NP) return;
    int b = gwarp / NP;
    int n = gwarp % NP;

    __shared__ float sh_probs[4][NCLS];
    __shared__ float sh_cen[4][3];

    const float* lg = logits + ((size_t)b * NP + n) * NCLS;
    float l0 = lg[lane], l1 = lg[lane + 32], l2 = lg[lane + 64], l3 = lg[lane + 96];
    float mx = fmaxf(fmaxf(l0, l1), fmaxf(l2, l3));
    #pragma unroll
    for (int o = 16; o; o >>= 1) mx = fmaxf(mx, __shfl_xor_sync(0xffffffffu, mx, o));
    float e0 = expf(l0 - mx), e1 = expf(l1 - mx), e2 = expf(l2 - mx), e3 = expf(l3 - mx);
    float s = e0 + e1 + e2 + e3;
    #pragma unroll
    for (int o = 16; o; o >>= 1) s += __shfl_xor_sync(0xffffffffu, s, o);
    sh_probs[wloc][lane]      = e0 / s;
    sh_probs[wloc][lane + 32] = e1 / s;
    sh_probs[wloc][lane + 64] = e2 / s;
    sh_probs[wloc][lane + 96] = e3 / s;

    const float* cr = corners + ((size_t)b * NP + n) * (KC * 3);
    if (lane < 3) {
        float sum = 0.0f;
        #pragma unroll
        for (int k = 0; k < KC; k++) sum += cr[k * 3 + lane];
        sh_cen[wloc][lane] = sum * 0.125f;
    }
    __syncwarp();

    float cx = sh_cen[wloc][0], cy = sh_cen[wloc][1], cz = sh_cen[wloc][2];

    #pragma unroll
    for (int t = 0; t < 2; t++) {
        int m = lane + t * 32;
        int lab = labels[b * MT + m];
        float cc = -sh_probs[wloc][lab];
        const float* bx = boxes + ((size_t)b * MT + m) * 7;
        float dx = cx - bx[0], dy = cy - bx[1], dz = cz - bx[2];
        float bc = sqrtf(dx * dx + dy * dy + dz * dz);
        float c = cc + 5.0f * bc;
        outC[((size_t)b * NP + n) * MT + m] = c;
        g_CT[((size_t)b * MT + m) * NP + n] = c;
    }
}

// ---------------------------------------------------------------------------
// Order-preserving float <-> u32 encoding for unsigned-min reductions.
// ---------------------------------------------------------------------------
__device__ __forceinline__ unsigned fenc(float f) {
    unsigned u = __float_as_uint(f);
    return u ^ (unsigned)(((int)u >> 31) | 0x80000000);
}
__device__ __forceinline__ float fdec(unsigned e) {
    unsigned u = (e & 0x80000000u) ? (e ^ 0x80000000u) : ~e;
    return __uint_as_float(u);
}

// ---------------------------------------------------------------------------
// Kernel 2: Jonker-Volgenant LSA, 8 warps (256 threads) per batch.
// Bit-exact float sequence vs the reference. Lane owns columns
// j = 1 + tid + 256k. v, minv, p, u in registers; used = 4-bit reg mask.
// Delta application deferred one iteration and fused into the scan.
// Warp winner lane writes (enc,j) AND (p,u) payload; one barrier per iter;
// cross-warp combine is a pairwise u64 min-tree with payload selection.
// ---------------------------------------------------------------------------
__global__ __launch_bounds__(TLSA, 1)
void lsa_kernel(float* __restrict__ out) {
    const int b    = blockIdx.x;
    const int tid  = threadIdx.x;
    const int wid  = tid >> 5;

    __shared__ int                p_sh[NP + 1];
    __shared__ float              u_sh[NP + 1];   // u_of_col[j] == u[p_sh[j]]
    __shared__ int                way_sh[NP + 1];
    __shared__ unsigned long long redbuf[2][8];   // (enc<<32)|j per warp
    __shared__ unsigned long long pubuf[2][8];    // (p<<32)|u_bits per warp

    for (int j = tid; j <= NP; j += TLSA) { p_sh[j] = 0; u_sh[j] = 0.0f; }
    __syncthreads();

    const float* CT = g_CT + (size_t)b * MT * NP;
    const int  jbase = 1 + tid;
    const bool v3    = (tid < NP - 3 * TLSA);   // tid < 132 -> k=3 valid

    float v[NPK], ureg[NPK], minv[NPK];
    int   preg[NPK];
    #pragma unroll
    for (int k = 0; k < NPK; k++) { v[k] = 0.0f; ureg[k] = 0.0f; preg[k] = 0; }

    for (int i1 = 1; i1 <= MT; i1++) {
        #pragma unroll
        for (int k = 0; k < NPK; k++) minv[k] = INF_F;
        unsigned usedm = 0;
        float u0col = 0.0f, pend = 0.0f, u0 = 0.0f;
        int   j0 = 0, i0 = i1;
        if (tid == 0) p_sh[0] = i1;     // only tid0 ever reads p_sh[0]

        for (int it = 0; it < MT + 8; it++) {
            if (i0 == 0) break;   // free column found; flush below

            // mark j0 used by its owner thread (j0==0 dummy excluded)
            unsigned newm = usedm;
            if (j0 > 0 && ((j0 - 1) & (TLSA - 1)) == tid)
                newm |= 1u << ((j0 - 1) >> 8);

            const float* rp = CT + (size_t)(i0 - 1) * NP + tid;

            unsigned bestenc = 0xFFFFFFFFu;
            int      bestj   = 0x7FFFFFFF;
            int      bestp   = 0;
            float    bestu   = 0.0f;
            #pragma unroll
            for (int k = 0; k < NPK; k++) {
                bool valid = (k < NPK - 1) | v3;
                if (valid) {
                    int j = jbase + TLSA * k;
                    // apply pending delta (old mask): used -> v,u ; unused -> minv
                    if ((usedm >> k) & 1) { v[k] -= pend; ureg[k] += pend; }
                    else                  minv[k] -= pend;
                    float cur = rp[TLSA * k] - u0 - v[k];
                    bool isused = (newm >> k) & 1;
                    if (!isused && cur < minv[k]) { minv[k] = cur; way_sh[j] = j0; }
                    float mv = isused ? INF_F : minv[k];
                    unsigned enc = fenc(mv);
                    if (enc < bestenc) {
                        bestenc = enc; bestj = j; bestp = preg[k]; bestu = ureg[k];
                    }
                }
            }
            u0col += pend;            // col 0 is always used: row i1's u
            usedm  = newm;

            // warp argmin: value first, then smallest j among tied lanes
            unsigned wenc = __reduce_min_sync(0xffffffffu, bestenc);
            unsigned cand = (bestenc == wenc) ? (unsigned)bestj : 0xFFFFFFFFu;
            unsigned wj   = __reduce_min_sync(0xffffffffu, cand);
            // unique winner lane (bestj unique per lane) writes its payload
            if (bestenc == wenc && (unsigned)bestj == wj) {
                redbuf[it & 1][wid] = ((unsigned long long)wenc << 32) | wj;
                pubuf [it & 1][wid] = ((unsigned long long)(unsigned)bestp << 32)
                                      | __float_as_uint(bestu);
            }
            __syncthreads();

            // cross-warp: u64 min over (enc,j) == (min enc, then min j); tree
            const unsigned long long* rb = redbuf[it & 1];
            const unsigned long long* pb = pubuf[it & 1];
            unsigned long long b0 = rb[0], b1 = rb[1], b2 = rb[2], b3 = rb[3];
            unsigned long long b4 = rb[4], b5 = rb[5], b6 = rb[6], b7 = rb[7];
            unsigned long long q0 = pb[0], q1 = pb[1], q2 = pb[2], q3 = pb[3];
            unsigned long long q4 = pb[4], q5 = pb[5], q6 = pb[6], q7 = pb[7];
            if (b1 < b0) { b0 = b1; q0 = q1; }
            if (b3 < b2) { b2 = b3; q2 = q3; }
            if (b5 < b4) { b4 = b5; q4 = q5; }
            if (b7 < b6) { b6 = b7; q6 = q7; }
            if (b2 < b0) { b0 = b2; q0 = q2; }
            if (b6 < b4) { b4 = b6; q4 = q6; }
            if (b4 < b0) { b0 = b4; q0 = q4; }

            j0   = (int)(unsigned)b0;
            pend = fdec((unsigned)(b0 >> 32));
            i0   = (int)(q0 >> 32);
            u0   = __uint_as_float((unsigned)q0);
        }

        // flush final pending delta to used columns; publish their u to smem
        #pragma unroll
        for (int k = 0; k < NPK; k++) {
            bool valid = (k < NPK - 1) | v3;
            if (valid && ((usedm >> k) & 1)) {
                v[k]    -= pend;
                ureg[k] += pend;
                u_sh[jbase + TLSA * k] = ureg[k];
            }
        }
        u0col += pend;
        if (tid == 0) u_sh[0] = u0col;
        __syncthreads();

        // backtrack augmenting path (serial, tid 0); copy u_of_col with p
        if (tid == 0) {
            int jj = j0;
            for (int s = 0; s < MT + 8 && jj != 0; s++) {
                int jn = way_sh[jj];
                p_sh[jj] = p_sh[jn];
                u_sh[jj] = u_sh[jn];
                jj = jn;
            }
        }
        __syncthreads();

        // reload register p/u mirrors for next phase
        #pragma unroll
        for (int k = 0; k < NPK; k++) {
            bool valid = (k < NPK - 1) | v3;
            if (valid) {
                preg[k] = p_sh[jbase + TLSA * k];
                ureg[k] = u_sh[jbase + TLSA * k];
            }
        }
    }

    // outputs: pred_idx (value-cast float), tgt_idx
    float* predf = out + (size_t)BB * NP * MT;
    float* tgtf  = predf + (size_t)BB * MT;
    for (int j = 1 + tid; j <= NP; j += TLSA) {
        int r = p_sh[j];
        if (r > 0) predf[b * MT + (r - 1)] = (float)(j - 1);
    }
    for (int m = tid; m < MT; m += TLSA) tgtf[b * MT + m] = (float)m;
}

// ---------------------------------------------------------------------------
extern "C" void kernel_launch(void* const* d_in, const int* in_sizes, int n_in,
                              void* d_out, int out_size) {
    const float* logits  = (const float*)d_in[0];   // [64, 900, 128]
    const float* corners = (const float*)d_in[1];   // [64, 900, 8, 3]
    const int*   labels  = (const int*)  d_in[2];   // [64, 64]
    const float* boxes   = (const float*)d_in[3];   // [64, 64, 7]
    float* out = (float*)d_out;

    (void)in_sizes; (void)n_in; (void)out_size;

    int warps  = BB * NP;
    int blocks = (warps + 3) / 4;
    cost_kernel<<<blocks, 128>>>(logits, corners, labels, boxes, out);

    lsa_kernel<<<BB, TLSA>>>(out);
}

// round 6
// speedup vs baseline: 1.2300x; 1.2300x over previous
#include <cuda_runtime.h>
#include <cuda_bf16.h>
#include <cstdint>

// Problem constants
#define BB   64     // batch
#define NP   900    // predictions (columns)
#define NCLS 128    // classes
#define MT   64     // targets (rows)
#define KC   8      // corners
#define INF_F 1000000000.0f

#define TLSA 128    // threads per LSA block (4 warps)
#define NPK  8      // ceil(900/128) columns per thread (tid<4 have 8, rest 7)

// Transposed cost scratch: CT[b][m][n], contiguous in n for fast row reads in LSA.
__device__ float g_CT[(size_t)BB * MT * NP];

// ---------------------------------------------------------------------------
// Kernel 1: cost matrix. One warp per (b, n). Block = 128 threads = 4 warps.
// ---------------------------------------------------------------------------
__global__ void cost_kernel(const float* __restrict__ logits,
                            const float* __restrict__ corners,
                            const int*   __restrict__ labels,
                            const float* __restrict__ boxes,
                            float* __restrict__ outC) {
    int gwarp = (blockIdx.x * blockDim.x + threadIdx.x) >> 5;
    int lane  = threadIdx.x & 31;
    int wloc  = threadIdx.x >> 5;
    if (gwarp >= BB * NP) return;
    int b = gwarp / NP;
    int n = gwarp % NP;

    __shared__ float sh_probs[4][NCLS];
    __shared__ float sh_cen[4][3];

    const float* lg = logits + ((size_t)b * NP + n) * NCLS;
    float l0 = lg[lane], l1 = lg[lane + 32], l2 = lg[lane + 64], l3 = lg[lane + 96];
    float mx = fmaxf(fmaxf(l0, l1), fmaxf(l2, l3));
    #pragma unroll
    for (int o = 16; o; o >>= 1) mx = fmaxf(mx, __shfl_xor_sync(0xffffffffu, mx, o));
    float e0 = expf(l0 - mx), e1 = expf(l1 - mx), e2 = expf(l2 - mx), e3 = expf(l3 - mx);
    float s = e0 + e1 + e2 + e3;
    #pragma unroll
    for (int o = 16; o; o >>= 1) s += __shfl_xor_sync(0xffffffffu, s, o);
    sh_probs[wloc][lane]      = e0 / s;
    sh_probs[wloc][lane + 32] = e1 / s;
    sh_probs[wloc][lane + 64] = e2 / s;
    sh_probs[wloc][lane + 96] = e3 / s;

    const float* cr = corners + ((size_t)b * NP + n) * (KC * 3);
    if (lane < 3) {
        float sum = 0.0f;
        #pragma unroll
        for (int k = 0; k < KC; k++) sum += cr[k * 3 + lane];
        sh_cen[wloc][lane] = sum * 0.125f;
    }
    __syncwarp();

    float cx = sh_cen[wloc][0], cy = sh_cen[wloc][1], cz = sh_cen[wloc][2];

    #pragma unroll
    for (int t = 0; t < 2; t++) {
        int m = lane + t * 32;
        int lab = labels[b * MT + m];
        float cc = -sh_probs[wloc][lab];
        const float* bx = boxes + ((size_t)b * MT + m) * 7;
        float dx = cx - bx[0], dy = cy - bx[1], dz = cz - bx[2];
        float bc = sqrtf(dx * dx + dy * dy + dz * dz);
        float c = cc + 5.0f * bc;
        outC[((size_t)b * NP + n) * MT + m] = c;
        g_CT[((size_t)b * MT + m) * NP + n] = c;
    }
}

// ---------------------------------------------------------------------------
// Order-preserving float <-> u32 encoding for unsigned-min reductions.
// ---------------------------------------------------------------------------
__device__ __forceinline__ unsigned fenc(float f) {
    unsigned u = __float_as_uint(f);
    return u ^ (unsigned)(((int)u >> 31) | 0x80000000);
}
__device__ __forceinline__ float fdec(unsigned e) {
    unsigned u = (e & 0x80000000u) ? (e ^ 0x80000000u) : ~e;
    return __uint_as_float(u);
}

// ---------------------------------------------------------------------------
// Kernel 2: JV LSA with row-reduction + greedy prefill. One block (128 thr,
// 4 warps) per batch. u[i] = min_j C[i,j]; rows whose argmin column is free
// are assigned directly; remaining rows run the shortest-augmenting-path
// phase (dual-feasible start => exact optimal assignment).
// Thread owns columns j = 1 + tid + 128k. v, minv, p, u mirrors in registers;
// used = 8-bit mask; delta deferred one iteration; winner-payload via smem.
// ---------------------------------------------------------------------------
__global__ __launch_bounds__(TLSA, 1)
void lsa_kernel(float* __restrict__ out) {
    const int b    = blockIdx.x;
    const int tid  = threadIdx.x;
    const int lane = tid & 31;
    const int wid  = tid >> 5;

    __shared__ int                p_sh[NP + 1];
    __shared__ float              u_sh[NP + 1];    // u_of_col[j] == u[p_sh[j]]
    __shared__ int                way_sh[NP + 1];
    __shared__ float              umin_sh[MT];     // row-reduction u
    __shared__ int                jmin_sh[MT];     // row argmin column (0-based)
    __shared__ int                ua_sh[MT];       // unassigned rows (1-based)
    __shared__ int                nua_sh;
    __shared__ unsigned long long redbuf[2][4];    // (enc<<32)|j per warp
    __shared__ unsigned long long pubuf[2][4];     // (p<<32)|u_bits per warp

    for (int j = tid; j <= NP; j += TLSA) { p_sh[j] = 0; u_sh[j] = 0.0f; }

    const float* CT = g_CT + (size_t)b * MT * NP;

    // ---- phase 0: per-row min + argmin (warp w handles rows w, w+4, ...) ----
    for (int r = wid; r < MT; r += 4) {
        const float* row = CT + (size_t)r * NP;
        float bm = INF_F; int bj = NP;
        for (int j = lane; j < NP; j += 32) {
            float c = row[j];
            if (c < bm) { bm = c; bj = j; }
        }
        unsigned enc  = fenc(bm);
        unsigned we   = __reduce_min_sync(0xffffffffu, enc);
        unsigned cand = (enc == we) ? (unsigned)bj : 0xFFFFFFFFu;
        unsigned wj   = __reduce_min_sync(0xffffffffu, cand);
        if (lane == 0) { umin_sh[r] = fdec(we); jmin_sh[r] = (int)wj; }
    }
    __syncthreads();

    // ---- greedy prefill (serial, tiny) ----
    if (tid == 0) {
        int nun = 0;
        for (int i = 0; i < MT; i++) {
            int j1 = jmin_sh[i] + 1;
            if (p_sh[j1] == 0) { p_sh[j1] = i + 1; u_sh[j1] = umin_sh[i]; }
            else ua_sh[nun++] = i + 1;
        }
        nua_sh = nun;
    }
    __syncthreads();

    const int  nua   = nua_sh;
    const int  jbase = 1 + tid;
    const bool v7    = (tid < NP - 7 * TLSA);   // tid < 4 -> k=7 valid

    float v[NPK], ureg[NPK], minv[NPK];
    int   preg[NPK];
    #pragma unroll
    for (int k = 0; k < NPK; k++) v[k] = 0.0f;

    // ---- augmenting phases for unassigned rows only ----
    for (int t = 0; t < nua; t++) {
        const int i1 = ua_sh[t];

        // reload register p/u mirrors (p_sh/u_sh stable since last barrier)
        #pragma unroll
        for (int k = 0; k < NPK; k++) {
            bool valid = (k < NPK - 1) | v7;
            if (valid) {
                preg[k] = p_sh[jbase + TLSA * k];
                ureg[k] = u_sh[jbase + TLSA * k];
            }
            minv[k] = INF_F;
        }
        unsigned usedm = 0;
        float u0col = umin_sh[i1 - 1];     // u of row i1 (column-0 carrier)
        float pend  = 0.0f;
        float u0    = u0col;
        int   j0    = 0, i0 = i1;
        if (tid == 0) p_sh[0] = i1;

        for (int it = 0; it < MT + 8; it++) {
            if (i0 == 0) break;   // free column found; flush below

            unsigned newm = usedm;
            if (j0 > 0 && ((j0 - 1) & (TLSA - 1)) == tid)
                newm |= 1u << ((j0 - 1) >> 7);

            const float* rp = CT + (size_t)(i0 - 1) * NP + tid;

            unsigned bestenc = 0xFFFFFFFFu;
            int      bestj   = 0x7FFFFFFF;
            int      bestp   = 0;
            float    bestu   = 0.0f;
            #pragma unroll
            for (int k = 0; k < NPK; k++) {
                bool valid = (k < NPK - 1) | v7;
                if (valid) {
                    int j = jbase + TLSA * k;
                    if ((usedm >> k) & 1) { v[k] -= pend; ureg[k] += pend; }
                    else                  minv[k] -= pend;
                    float cur = rp[TLSA * k] - u0 - v[k];
                    bool isused = (newm >> k) & 1;
                    if (!isused && cur < minv[k]) { minv[k] = cur; way_sh[j] = j0; }
                    float mv = isused ? INF_F : minv[k];
                    unsigned enc = fenc(mv);
                    if (enc < bestenc) {
                        bestenc = enc; bestj = j; bestp = preg[k]; bestu = ureg[k];
                    }
                }
            }
            u0col += pend;
            usedm  = newm;

            // warp argmin: value first, then smallest j among tied lanes
            unsigned wenc = __reduce_min_sync(0xffffffffu, bestenc);
            unsigned cand = (bestenc == wenc) ? (unsigned)bestj : 0xFFFFFFFFu;
            unsigned wj   = __reduce_min_sync(0xffffffffu, cand);
            if (bestenc == wenc && (unsigned)bestj == wj) {
                redbuf[it & 1][wid] = ((unsigned long long)wenc << 32) | wj;
                pubuf [it & 1][wid] = ((unsigned long long)(unsigned)bestp << 32)
                                      | __float_as_uint(bestu);
            }
            __syncthreads();

            const unsigned long long* rb = redbuf[it & 1];
            const unsigned long long* pb = pubuf[it & 1];
            unsigned long long b0 = rb[0], b1 = rb[1], b2 = rb[2], b3 = rb[3];
            unsigned long long q0 = pb[0], q1 = pb[1], q2 = pb[2], q3 = pb[3];
            if (b1 < b0) { b0 = b1; q0 = q1; }
            if (b3 < b2) { b2 = b3; q2 = q3; }
            if (b2 < b0) { b0 = b2; q0 = q2; }

            j0   = (int)(unsigned)b0;
            pend = fdec((unsigned)(b0 >> 32));
            i0   = (int)(q0 >> 32);
            u0   = __uint_as_float((unsigned)q0);
        }

        // flush final pending delta; publish used columns' u to smem
        #pragma unroll
        for (int k = 0; k < NPK; k++) {
            bool valid = (k < NPK - 1) | v7;
            if (valid && ((usedm >> k) & 1)) {
                v[k]    -= pend;
                ureg[k] += pend;
                u_sh[jbase + TLSA * k] = ureg[k];
            }
        }
        u0col += pend;
        if (tid == 0) u_sh[0] = u0col;
        __syncthreads();

        // backtrack augmenting path (serial, tid 0); copy u_of_col with p
        if (tid == 0) {
            int jj = j0;
            for (int s = 0; s < MT + 8 && jj != 0; s++) {
                int jn = way_sh[jj];
                p_sh[jj] = p_sh[jn];
                u_sh[jj] = u_sh[jn];
                jj = jn;
            }
        }
        __syncthreads();
    }

    // outputs: pred_idx (value-cast float), tgt_idx
    float* predf = out + (size_t)BB * NP * MT;
    float* tgtf  = predf + (size_t)BB * MT;
    for (int j = 1 + tid; j <= NP; j += TLSA) {
        int r = p_sh[j];
        if (r > 0) predf[b * MT + (r - 1)] = (float)(j - 1);
    }
    for (int m = tid; m < MT; m += TLSA) tgtf[b * MT + m] = (float)m;
}

// ---------------------------------------------------------------------------
extern "C" void kernel_launch(void* const* d_in, const int* in_sizes, int n_in,
                              void* d_out, int out_size) {
    const float* logits  = (const float*)d_in[0];   // [64, 900, 128]
    const float* corners = (const float*)d_in[1];   // [64, 900, 8, 3]
    const int*   labels  = (const int*)  d_in[2];   // [64, 64]
    const float* boxes   = (const float*)d_in[3];   // [64, 64, 7]
    float* out = (float*)d_out;

    (void)in_sizes; (void)n_in; (void)out_size;

    int warps  = BB * NP;
    int blocks = (warps + 3) / 4;
    cost_kernel<<<blocks, 128>>>(logits, corners, labels, boxes, out);

    lsa_kernel<<<BB, TLSA>>>(out);
}

// round 7
// speedup vs baseline: 1.3320x; 1.0829x over previous
#include <cuda_runtime.h>
#include <cuda_bf16.h>
#include <cstdint>

// Problem constants
#define BB   64     // batch
#define NP   900    // predictions (columns)
#define NCLS 128    // classes
#define MT   64     // targets (rows)
#define KC   8      // corners
#define INF_F 1000000000.0f

#define TLSA 128    // threads per LSA block (4 warps)
#define NPK  8      // ceil(900/128) columns per thread (tid<4 have 8, rest 7)
#define NTILE 32    // n-tile per cost block
#define ARR_CAP 96  // max augmenting-row-reduction steps

// Transposed cost scratch: CT[b][m][n], contiguous in n for fast row reads in LSA.
__device__ float g_CT[(size_t)BB * MT * NP];

// ---------------------------------------------------------------------------
// Kernel 1: cost matrix. Block = (one b, 32 n), 4 warps x 8 n each.
// outC[b][n][m] written directly (coalesced); CT[b][m][n] via smem transpose
// so every CT store is a 128B coalesced row segment.
// ---------------------------------------------------------------------------
__global__ __launch_bounds__(128)
void cost_kernel(const float* __restrict__ logits,
                 const float* __restrict__ corners,
                 const int*   __restrict__ labels,
                 const float* __restrict__ boxes,
                 float* __restrict__ outC) {
    const int b    = blockIdx.y;
    const int n0   = blockIdx.x * NTILE;
    const int lane = threadIdx.x & 31;
    const int wid  = threadIdx.x >> 5;

    __shared__ float tile[MT][NTILE + 1];
    __shared__ float sh_probs[4][NCLS];
    __shared__ float sh_cen[4][3];
    __shared__ int   sh_lab[MT];
    __shared__ float sh_box[MT][3];

    if (threadIdx.x < MT) {
        sh_lab[threadIdx.x] = labels[b * MT + threadIdx.x];
        const float* bx = boxes + ((size_t)b * MT + threadIdx.x) * 7;
        sh_box[threadIdx.x][0] = bx[0];
        sh_box[threadIdx.x][1] = bx[1];
        sh_box[threadIdx.x][2] = bx[2];
    }
    __syncthreads();

    #pragma unroll
    for (int q = 0; q < 8; q++) {
        int n = n0 + wid * 8 + q;
        if (n < NP) {
            const float* lg = logits + ((size_t)b * NP + n) * NCLS;
            float l0 = lg[lane], l1 = lg[lane + 32], l2 = lg[lane + 64], l3 = lg[lane + 96];
            float mx = fmaxf(fmaxf(l0, l1), fmaxf(l2, l3));
            #pragma unroll
            for (int o = 16; o; o >>= 1) mx = fmaxf(mx, __shfl_xor_sync(0xffffffffu, mx, o));
            float e0 = expf(l0 - mx), e1 = expf(l1 - mx), e2 = expf(l2 - mx), e3 = expf(l3 - mx);
            float s = e0 + e1 + e2 + e3;
            #pragma unroll
            for (int o = 16; o; o >>= 1) s += __shfl_xor_sync(0xffffffffu, s, o);
            sh_probs[wid][lane]      = e0 / s;
            sh_probs[wid][lane + 32] = e1 / s;
            sh_probs[wid][lane + 64] = e2 / s;
            sh_probs[wid][lane + 96] = e3 / s;

            const float* cr = corners + ((size_t)b * NP + n) * (KC * 3);
            if (lane < 3) {
                float sum = 0.0f;
                #pragma unroll
                for (int k = 0; k < KC; k++) sum += cr[k * 3 + lane];
                sh_cen[wid][lane] = sum * 0.125f;
            }
            __syncwarp();
            float cx = sh_cen[wid][0], cy = sh_cen[wid][1], cz = sh_cen[wid][2];

            #pragma unroll
            for (int t = 0; t < 2; t++) {
                int m = lane + t * 32;
                float cc = -sh_probs[wid][sh_lab[m]];
                float dx = cx - sh_box[m][0], dy = cy - sh_box[m][1], dz = cz - sh_box[m][2];
                float c = cc + 5.0f * sqrtf(dx * dx + dy * dy + dz * dz);
                outC[((size_t)b * NP + n) * MT + m] = c;
                tile[m][n - n0] = c;
            }
        }
    }
    __syncthreads();

    // coalesced CT writes: warp writes a 128B row segment per iteration
    #pragma unroll
    for (int r = 0; r < 16; r++) {
        int m = wid * 16 + r;
        int n = n0 + lane;
        if (n < NP) g_CT[((size_t)b * MT + m) * NP + n] = tile[m][lane];
    }
}

// ---------------------------------------------------------------------------
// Order-preserving float <-> u32 encoding for unsigned-min reductions.
// ---------------------------------------------------------------------------
__device__ __forceinline__ unsigned fenc(float f) {
    unsigned u = __float_as_uint(f);
    return u ^ (unsigned)(((int)u >> 31) | 0x80000000);
}
__device__ __forceinline__ float fdec(unsigned e) {
    unsigned u = (e & 0x80000000u) ? (e ^ 0x80000000u) : ~e;
    return __uint_as_float(u);
}

// merge two sorted (a1<=a2) top-2 u64 sets
__device__ __forceinline__ void top2_merge(unsigned long long& a1, unsigned long long& a2,
                                           unsigned long long b1, unsigned long long b2) {
    if (b1 < a1) { a2 = (a1 < b2) ? a1 : b2; a1 = b1; }
    else         { a2 = (a2 < b1) ? a2 : b1; }
}

// ---------------------------------------------------------------------------
// Kernel 2: JV LSA: row-reduction + greedy prefill + augmenting row reduction
// + exact shortest-augmenting-path for any leftovers. One block per batch,
// 128 threads (4 warps). Thread owns columns j = 1 + tid + 128k.
// ---------------------------------------------------------------------------
__global__ __launch_bounds__(TLSA, 1)
void lsa_kernel(float* __restrict__ out) {
    const int b    = blockIdx.x;
    const int tid  = threadIdx.x;
    const int lane = tid & 31;
    const int wid  = tid >> 5;

    __shared__ int                p_sh[NP + 1];
    __shared__ float              u_sh[NP + 1];    // u_of_col[j] == u[p_sh[j]]
    __shared__ int                way_sh[NP + 1];
    __shared__ float              umin_sh[MT];     // row-reduction u
    __shared__ int                jmin_sh[MT];     // row argmin column (0-based)
    __shared__ int                ua_sh[256];      // worklist of rows (1-based)
    __shared__ int                head_sh, cnt_sh;
    __shared__ unsigned long long redbuf[2][4];    // (enc<<32)|j per warp
    __shared__ unsigned long long pubuf[2][4];     // (p<<32)|u_bits per warp
    __shared__ unsigned long long t2buf[4][2];     // per-warp top-2 for ARR

    for (int j = tid; j <= NP; j += TLSA) { p_sh[j] = 0; u_sh[j] = 0.0f; }

    const float* CT = g_CT + (size_t)b * MT * NP;

    // ---- phase 0: per-row min + argmin (warp w handles rows w, w+4, ...) ----
    for (int r = wid; r < MT; r += 4) {
        const float* row = CT + (size_t)r * NP;
        float bm = INF_F; int bj = NP;
        for (int j = lane; j < NP; j += 32) {
            float c = row[j];
            if (c < bm) { bm = c; bj = j; }
        }
        unsigned enc  = fenc(bm);
        unsigned we   = __reduce_min_sync(0xffffffffu, enc);
        unsigned cand = (enc == we) ? (unsigned)bj : 0xFFFFFFFFu;
        unsigned wj   = __reduce_min_sync(0xffffffffu, cand);
        if (lane == 0) { umin_sh[r] = fdec(we); jmin_sh[r] = (int)wj; }
    }
    __syncthreads();

    // ---- greedy prefill (serial, tiny) ----
    if (tid == 0) {
        int nun = 0;
        for (int i = 0; i < MT; i++) {
            int j1 = jmin_sh[i] + 1;
            if (p_sh[j1] == 0) { p_sh[j1] = i + 1; u_sh[j1] = umin_sh[i]; }
            else ua_sh[nun++] = i + 1;
        }
        head_sh = 0; cnt_sh = nun;
    }

    const int  jbase = 1 + tid;
    const bool v7    = (tid < NP - 7 * TLSA);   // tid < 4 -> k=7 valid

    float v[NPK], ureg[NPK], minv[NPK];
    int   preg[NPK];
    #pragma unroll
    for (int k = 0; k < NPK; k++) v[k] = 0.0f;

    // ---- augmenting row reduction (JV init) ----
    for (int step = 0; step < ARR_CAP; step++) {
        __syncthreads();
        int head = head_sh, cnt = cnt_sh;
        if (head >= cnt) break;
        const int i = ua_sh[head];
        const float* rp = CT + (size_t)(i - 1) * NP + tid;

        // per-thread top-2 of d_j = C[i-1][j-1] - v[j], packed (enc<<32)|j
        unsigned long long a1 = ~0ull, a2 = ~0ull;
        #pragma unroll
        for (int k = 0; k < NPK; k++) {
            bool valid = (k < NPK - 1) | v7;
            if (valid) {
                float d = rp[TLSA * k] - v[k];
                unsigned long long x =
                    ((unsigned long long)fenc(d) << 32) | (unsigned)(jbase + TLSA * k);
                if (x < a1) { a2 = a1; a1 = x; }
                else if (x < a2) a2 = x;
            }
        }
        // warp top-2 merge
        #pragma unroll
        for (int o = 16; o; o >>= 1) {
            unsigned long long b1 = __shfl_xor_sync(0xffffffffu, a1, o);
            unsigned long long b2 = __shfl_xor_sync(0xffffffffu, a2, o);
            top2_merge(a1, a2, b1, b2);
        }
        if (lane == 0) { t2buf[wid][0] = a1; t2buf[wid][1] = a2; }
        __syncthreads();
        unsigned long long g1 = t2buf[0][0], g2 = t2buf[0][1];
        top2_merge(g1, g2, t2buf[1][0], t2buf[1][1]);
        top2_merge(g1, g2, t2buf[2][0], t2buf[2][1]);
        top2_merge(g1, g2, t2buf[3][0], t2buf[3][1]);

        unsigned u1enc = (unsigned)(g1 >> 32); int j1 = (int)(unsigned)g1;
        unsigned u2enc = (unsigned)(g2 >> 32); int j2 = (int)(unsigned)g2;
        bool strict = (u1enc < u2enc);
        int  i1old  = p_sh[j1];
        int  jassign = strict ? j1 : (i1old > 0 ? j2 : j1);

        // column dual update by owner of j1 (strict branch only)
        if (strict && ((j1 - 1) & (TLSA - 1)) == tid)
            v[(j1 - 1) >> 7] -= (fdec(u2enc) - fdec(u1enc));

        if (tid == 0) {
            int bumped = p_sh[jassign];
            p_sh[jassign] = i;
            u_sh[jassign] = strict ? fdec(u2enc) : fdec(u1enc);
            head_sh = head + 1;
            if (bumped > 0) { ua_sh[cnt] = bumped; cnt_sh = cnt + 1; }
        }
    }
    __syncthreads();

    const int t0 = head_sh, t1 = cnt_sh;
    __syncthreads();

    // ---- exact shortest-augmenting-path for leftover rows ----
    for (int t = t0; t < t1; t++) {
        const int i1 = ua_sh[t];

        #pragma unroll
        for (int k = 0; k < NPK; k++) {
            bool valid = (k < NPK - 1) | v7;
            if (valid) {
                preg[k] = p_sh[jbase + TLSA * k];
                ureg[k] = u_sh[jbase + TLSA * k];
            }
            minv[k] = INF_F;
        }
        unsigned usedm = 0;
        float u0col = umin_sh[i1 - 1];     // feasible u for row i1
        float pend  = 0.0f;
        float u0    = u0col;
        int   j0    = 0, i0 = i1;
        if (tid == 0) p_sh[0] = i1;

        for (int it = 0; it < MT + 8; it++) {
            if (i0 == 0) break;

            unsigned newm = usedm;
            if (j0 > 0 && ((j0 - 1) & (TLSA - 1)) == tid)
                newm |= 1u << ((j0 - 1) >> 7);

            const float* rp = CT + (size_t)(i0 - 1) * NP + tid;

            unsigned bestenc = 0xFFFFFFFFu;
            int      bestj   = 0x7FFFFFFF;
            int      bestp   = 0;
            float    bestu   = 0.0f;
            #pragma unroll
            for (int k = 0; k < NPK; k++) {
                bool valid = (k < NPK - 1) | v7;
                if (valid) {
                    int j = jbase + TLSA * k;
                    if ((usedm >> k) & 1) { v[k] -= pend; ureg[k] += pend; }
                    else                  minv[k] -= pend;
                    float cur = rp[TLSA * k] - u0 - v[k];
                    bool isused = (newm >> k) & 1;
                    if (!isused && cur < minv[k]) { minv[k] = cur; way_sh[j] = j0; }
                    float mv = isused ? INF_F : minv[k];
                    unsigned enc = fenc(mv);
                    if (enc < bestenc) {
                        bestenc = enc; bestj = j; bestp = preg[k]; bestu = ureg[k];
                    }
                }
            }
            u0col += pend;
            usedm  = newm;

            unsigned wenc = __reduce_min_sync(0xffffffffu, bestenc);
            unsigned cand = (bestenc == wenc) ? (unsigned)bestj : 0xFFFFFFFFu;
            unsigned wj   = __reduce_min_sync(0xffffffffu, cand);
            if (bestenc == wenc && (unsigned)bestj == wj) {
                redbuf[it & 1][wid] = ((unsigned long long)wenc << 32) | wj;
                pubuf [it & 1][wid] = ((unsigned long long)(unsigned)bestp << 32)
                                      | __float_as_uint(bestu);
            }
            __syncthreads();

            const unsigned long long* rb = redbuf[it & 1];
            const unsigned long long* pb = pubuf[it & 1];
            unsigned long long b0 = rb[0], b1 = rb[1], b2 = rb[2], b3 = rb[3];
            unsigned long long q0 = pb[0], q1 = pb[1], q2 = pb[2], q3 = pb[3];
            if (b1 < b0) { b0 = b1; q0 = q1; }
            if (b3 < b2) { b2 = b3; q2 = q3; }
            if (b2 < b0) { b0 = b2; q0 = q2; }

            j0   = (int)(unsigned)b0;
            pend = fdec((unsigned)(b0 >> 32));
            i0   = (int)(q0 >> 32);
            u0   = __uint_as_float((unsigned)q0);
        }

        #pragma unroll
        for (int k = 0; k < NPK; k++) {
            bool valid = (k < NPK - 1) | v7;
            if (valid && ((usedm >> k) & 1)) {
                v[k]    -= pend;
                ureg[k] += pend;
                u_sh[jbase + TLSA * k] = ureg[k];
            }
        }
        u0col += pend;
        if (tid == 0) u_sh[0] = u0col;
        __syncthreads();

        if (tid == 0) {
            int jj = j0;
            for (int s = 0; s < MT + 8 && jj != 0; s++) {
                int jn = way_sh[jj];
                p_sh[jj] = p_sh[jn];
                u_sh[jj] = u_sh[jn];
                jj = jn;
            }
        }
        __syncthreads();
    }

    // outputs: pred_idx (value-cast float), tgt_idx
    float* predf = out + (size_t)BB * NP * MT;
    float* tgtf  = predf + (size_t)BB * MT;
    for (int j = 1 + tid; j <= NP; j += TLSA) {
        int r = p_sh[j];
        if (r > 0) predf[b * MT + (r - 1)] = (float)(j - 1);
    }
    for (int m = tid; m < MT; m += TLSA) tgtf[b * MT + m] = (float)m;
}

// ---------------------------------------------------------------------------
extern "C" void kernel_launch(void* const* d_in, const int* in_sizes, int n_in,
                              void* d_out, int out_size) {
    const float* logits  = (const float*)d_in[0];   // [64, 900, 128]
    const float* corners = (const float*)d_in[1];   // [64, 900, 8, 3]
    const int*   labels  = (const int*)  d_in[2];   // [64, 64]
    const float* boxes   = (const float*)d_in[3];   // [64, 64, 7]
    float* out = (float*)d_out;

    (void)in_sizes; (void)n_in; (void)out_size;

    dim3 cgrid((NP + NTILE - 1) / NTILE, BB);       // 29 x 64
    cost_kernel<<<cgrid, 128>>>(logits, corners, labels, boxes, out);

    lsa_kernel<<<BB, TLSA>>>(out);
}